// round 11
// baseline (speedup 1.0000x reference)
#include <cuda_runtime.h>

#define A_DIM 1024
#define T_DIM 256
#define CS 384
#define CZ 128
#define CA 128
#define CP 16
#define EPS 1e-5f

// ---- device scratch ----
__device__ int   g_tok[A_DIM];
__device__ int   g_order[A_DIM];     // atoms sorted by token
__device__ int   g_stok[A_DIM];      // token of sorted atom
__device__ int   g_start[T_DIM + 1]; // CSR offsets
__device__ float g_ys[T_DIM * CA];
__device__ int   g_flag[32];         // tok-block completion flags (reset each run)

#define FMA2(d, a, b) asm("fma.rn.f32x2 %0, %1, %2, %0;" : "+l"(d) : "l"(a), "l"(b))
#define ADD2(d, a)    asm("add.rn.f32x2 %0, %0, %1;" : "+l"(d) : "l"(a))

__device__ __forceinline__ float hsum2(unsigned long long v) {
    float lo, hi;
    asm("mov.b64 {%0, %1}, %2;" : "=f"(lo), "=f"(hi) : "l"(v));
    return lo + hi;
}

// ================= k_pre =================
// blocks [0,32)  : tok recovery (32 atom rows each) + flag
// blocks [32,64) : ys (8 tokens each)
// block 64       : counting sort -> g_order/g_stok/g_start (spins on flags)
__global__ __launch_bounds__(256) void k_pre(
    const float* __restrict__ a2t, const float* __restrict__ s_trunk,
    const float* __restrict__ gs, const float* __restrict__ bs,
    const float* __restrict__ Ws) {
    asm volatile("griddepcontrol.launch_dependents;");
    int tid = threadIdx.x;
    int bx = blockIdx.x;

    if (bx < 32) {
        int row0 = bx * 32;
#pragma unroll
        for (int i = 0; i < 32; i++) {
            float v = a2t[(size_t)(row0 + i) * T_DIM + tid];
            if (v > 0.5f) g_tok[row0 + i] = tid;
        }
        __syncthreads();
        __threadfence();
        if (tid == 0) atomicExch(&g_flag[bx], 1);
        return;
    }

    if (bx < 64) {
        // ---------- ys: 8 tokens per block ----------
        __shared__ float sn[8][CS];
        __shared__ float mv[8][2];
        int t0 = (bx - 32) * 8;
        int w = tid >> 5, lane = tid & 31;
        {
            int t = t0 + w;
            float s1 = 0.f, s2 = 0.f;
#pragma unroll
            for (int i = 0; i < 12; i++) {
                int k = lane + 32 * i;
                float x = s_trunk[(size_t)t * CS + k];
                sn[w][k] = x;
                s1 += x;
                s2 = fmaf(x, x, s2);
            }
            for (int d = 16; d; d >>= 1) {
                s1 += __shfl_down_sync(0xffffffffu, s1, d);
                s2 += __shfl_down_sync(0xffffffffu, s2, d);
            }
            if (lane == 0) {
                float m = s1 * (1.0f / CS);
                float v = s2 * (1.0f / CS) - m * m;
                mv[w][0] = m;
                mv[w][1] = rsqrtf(v + EPS);
            }
        }
        __syncthreads();
#pragma unroll
        for (int i = 0; i < 12; i++) {
            int idx = tid + 256 * i;
            int r = idx / CS, k = idx - r * CS;
            sn[r][k] = (sn[r][k] - mv[r][0]) * mv[r][1] * gs[k] + bs[k];
        }
        __syncthreads();
        int j = tid & 127;
        int h = tid >> 7;
        float a0 = 0.f, a1 = 0.f, a2 = 0.f, a3 = 0.f;
#pragma unroll 16
        for (int k = 0; k < CS; k++) {
            float wv = Ws[(size_t)k * CA + j];
            a0 = fmaf(sn[4*h  ][k], wv, a0);
            a1 = fmaf(sn[4*h+1][k], wv, a1);
            a2 = fmaf(sn[4*h+2][k], wv, a2);
            a3 = fmaf(sn[4*h+3][k], wv, a3);
        }
        g_ys[(size_t)(t0 + 4*h    ) * CA + j] = a0;
        g_ys[(size_t)(t0 + 4*h + 1) * CA + j] = a1;
        g_ys[(size_t)(t0 + 4*h + 2) * CA + j] = a2;
        g_ys[(size_t)(t0 + 4*h + 3) * CA + j] = a3;
        return;
    }

    // ---------- sort block ----------
    if (tid < 32) {
        while (atomicAdd(&g_flag[tid], 0) == 0) {}
    }
    __syncthreads();
    __threadfence();
    __shared__ int cnt[T_DIM];
    cnt[tid] = 0;
    __syncthreads();
    int t4[4];
#pragma unroll
    for (int i = 0; i < 4; i++) {
        t4[i] = g_tok[tid + 256 * i];
        atomicAdd(&cnt[t4[i]], 1);
    }
    __syncthreads();
    if (tid == 0) {
        int s = 0;
        for (int i = 0; i < T_DIM; i++) { int c = cnt[i]; cnt[i] = s; s += c; }
    }
    __syncthreads();
    g_start[tid] = cnt[tid];
    if (tid == 0) g_start[T_DIM] = A_DIM;
    __syncthreads();
#pragma unroll
    for (int i = 0; i < 4; i++) {
        int p = atomicAdd(&cnt[t4[i]], 1);
        g_order[p] = tid + 256 * i;
        g_stok[p] = t4[i];
    }
    __syncthreads();
    if (tid < 32) g_flag[tid] = 0;   // reset for next graph replay
}

// ================= k_fused =================
// blocks [0,128)     : clql
// blocks [128,4224)  : plm, block = (t, u-tile of 16 tokens): compute w in smem, apply
__global__ __launch_bounds__(256) void k_fused(
    const float* __restrict__ cl, const float* __restrict__ ql,
    const float* __restrict__ rl, const float* __restrict__ Wr,
    const float* __restrict__ plm, const float* __restrict__ zij,
    const float* __restrict__ gz, const float* __restrict__ bz,
    const float* __restrict__ Wz,
    float* __restrict__ out_cl, float* __restrict__ out_ql,
    float* __restrict__ out_plm) {
    int tid = threadIdx.x;
    int bx = blockIdx.x;

    if (bx < 128) {
        int a = bx * 8 + (tid >> 5);
        int j4 = tid & 31;
        size_t idx = (size_t)a * 32 + j4;
        const float4* cl4 = (const float4*)cl;
        const float4* ql4 = (const float4*)ql;
        const float4* ys4 = (const float4*)g_ys;
        const float4* Wr4 = (const float4*)Wr;
        float4 c = cl4[idx];
        float4 qv = ql4[idx];
        float r0 = rl[a * 3], r1 = rl[a * 3 + 1], r2 = rl[a * 3 + 2];
        float4 w0 = Wr4[j4], w1 = Wr4[32 + j4], w2 = Wr4[64 + j4];
        float4 oq;
        oq.x = qv.x + r0 * w0.x + r1 * w1.x + r2 * w2.x;
        oq.y = qv.y + r0 * w0.y + r1 * w1.y + r2 * w2.y;
        oq.z = qv.z + r0 * w0.z + r1 * w1.z + r2 * w2.z;
        oq.w = qv.w + r0 * w0.w + r1 * w1.w + r2 * w2.w;
        ((float4*)out_ql)[idx] = oq;
        asm volatile("griddepcontrol.wait;" ::: "memory");
        int ta = g_tok[a];
        float4 y = ys4[(size_t)ta * 32 + j4];
        float4 oc;
        oc.x = c.x + y.x; oc.y = c.y + y.y; oc.z = c.z + y.z; oc.w = c.w + y.w;
        ((float4*)out_cl)[idx] = oc;
        return;
    }

    // ---------- fused w + plm ----------
    int pm = bx - 128;
    int t = pm >> 4;
    int u0 = (pm & 15) * 16;

    __shared__ __align__(16) float zs[16 * 132];   // z rows, pad 132
    __shared__ __align__(16) float gw[16 * 132];   // GW[j][k], pad 132
    __shared__ __align__(16) float ws[16 * 20];    // w_s[u][j], pad 20
    __shared__ float ms[16], rs[16];
    __shared__ float bwv[CP], cgwv[CP];
    __shared__ float pbw[256], pcg[256];

    // 1. load z tile: 16 rows x 128 floats, coalesced
#pragma unroll
    for (int i = 0; i < 8; i++) {
        int idx = tid + 256 * i;
        int r = idx >> 7, k = idx & 127;
        zs[r * 132 + k] = zij[((size_t)(t * T_DIM + u0 + r)) * CZ + k];
    }
    // 2. GW + partials (Wz layout: [k][j], k row-major)
    {
        int j = tid & 15;
        float pb = 0.f, pc = 0.f;
#pragma unroll
        for (int i = 0; i < 8; i++) {
            int idx = tid + 256 * i;
            int k = idx >> 4;
            float wv = Wz[idx];
            float gg = gz[k] * wv;
            gw[j * 132 + k] = gg;
            pb = fmaf(bz[k], wv, pb);
            pc += gg;
        }
        pbw[tid] = pb;
        pcg[tid] = pc;
    }
    __syncthreads();
    if (tid < CP) {
        float sb = 0.f, sc = 0.f;
#pragma unroll
        for (int i = 0; i < 16; i++) {
            sb += pbw[tid + 16 * i];
            sc += pcg[tid + 16 * i];
        }
        bwv[tid] = sb;
        cgwv[tid] = sc;
    }

    // 3. LN stats: thread (u = tid>>4, g = tid&15), 8 k's each
    {
        int u = tid >> 4, g = tid & 15;
        float s1 = 0.f, s2 = 0.f;
#pragma unroll
        for (int i = 0; i < 8; i++) {
            float v = zs[u * 132 + g * 8 + i];
            s1 += v;
            s2 = fmaf(v, v, s2);
        }
        s1 += __shfl_xor_sync(0xffffffffu, s1, 1);
        s2 += __shfl_xor_sync(0xffffffffu, s2, 1);
        s1 += __shfl_xor_sync(0xffffffffu, s1, 2);
        s2 += __shfl_xor_sync(0xffffffffu, s2, 2);
        s1 += __shfl_xor_sync(0xffffffffu, s1, 4);
        s2 += __shfl_xor_sync(0xffffffffu, s2, 4);
        s1 += __shfl_xor_sync(0xffffffffu, s1, 8);
        s2 += __shfl_xor_sync(0xffffffffu, s2, 8);
        if (g == 0) {
            float m = s1 * (1.0f / CZ);
            float v = s2 * (1.0f / CZ) - m * m;
            ms[u] = m;
            rs[u] = rsqrtf(v + EPS);
        }
    }
    __syncthreads();

    // 4. GEMM: thread (u = tid>>4, j = tid&15): ws[u][j]
    {
        int u = tid >> 4, j = tid & 15;
        const ulonglong2* zr = (const ulonglong2*)(zs + u * 132);
        const ulonglong2* gr = (const ulonglong2*)(gw + j * 132);
        unsigned long long acc = 0ull;
#pragma unroll
        for (int k4 = 0; k4 < 32; k4++) {
            ulonglong2 zv = zr[k4], gv = gr[k4];
            FMA2(acc, zv.x, gv.x);
            FMA2(acc, zv.y, gv.y);
        }
        ws[u * 20 + j] = rs[u] * (hsum2(acc) - ms[u] * cgwv[j]) + bwv[j];
    }
    __syncthreads();

    // 5. wait for k_pre (CSR + tok)
    asm volatile("griddepcontrol.wait;" ::: "memory");

    int astart = g_start[t], aend = g_start[t + 1];
    int bstart = g_start[u0], bend = g_start[u0 + 16];
    int nb = bend - bstart;

    int c4 = tid & 3;
    int ibl = tid >> 2;            // 0..63
    const float4* p4 = (const float4*)plm;
    float4* o4 = (float4*)out_plm;

    for (int ia = astart; ia < aend; ia++) {
        int a = g_order[ia];       // uniform across block
        for (int ib0 = 0; ib0 < nb; ib0 += 64) {
            int ib = ib0 + ibl;
            if (ib < nb) {
                int b  = g_order[bstart + ib];
                int ul = g_stok[bstart + ib] - u0;
                size_t pi = ((size_t)a * A_DIM + b) * 4 + c4;
                float4 p = __ldcs(&p4[pi]);
                float4 wv = *((const float4*)&ws[ul * 20 + c4 * 4]);
                float4 o;
                o.x = p.x + wv.x; o.y = p.y + wv.y;
                o.z = p.z + wv.z; o.w = p.w + wv.w;
                __stcs(&o4[pi], o);
            }
        }
    }
}

extern "C" void kernel_launch(void* const* d_in, const int* in_sizes, int n_in,
                              void* d_out, int out_size) {
    const float* a2t     = (const float*)d_in[0];
    const float* cl      = (const float*)d_in[1];
    const float* plm     = (const float*)d_in[2];
    const float* ql      = (const float*)d_in[3];
    const float* s_trunk = (const float*)d_in[4];
    const float* zij     = (const float*)d_in[5];
    const float* rl      = (const float*)d_in[6];
    const float* ln_s_g  = (const float*)d_in[7];
    const float* ln_s_b  = (const float*)d_in[8];
    const float* Ws      = (const float*)d_in[9];
    const float* ln_z_g  = (const float*)d_in[10];
    const float* ln_z_b  = (const float*)d_in[11];
    const float* Wz      = (const float*)d_in[12];
    const float* Wr      = (const float*)d_in[13];
    float* out     = (float*)d_out;
    float* out_cl  = out;
    float* out_plm = out + A_DIM * CA;
    float* out_ql  = out_plm + (size_t)A_DIM * A_DIM * CP;

    k_pre<<<65, 256>>>(a2t, s_trunk, ln_s_g, ln_s_b, Ws);

    {
        cudaLaunchConfig_t cfg = {};
        cfg.gridDim = dim3(128 + T_DIM * 16);
        cfg.blockDim = dim3(256);
        cfg.dynamicSmemBytes = 0;
        cfg.stream = 0;
        cudaLaunchAttribute attrs[1];
        attrs[0].id = cudaLaunchAttributeProgrammaticStreamSerialization;
        attrs[0].val.programmaticStreamSerializationAllowed = 1;
        cfg.attrs = attrs;
        cfg.numAttrs = 1;
        cudaLaunchKernelEx(&cfg, k_fused, cl, ql, rl, Wr, plm, zij,
                           ln_z_g, ln_z_b, Wz, out_cl, out_ql, out_plm);
    }
}

// round 12
// speedup vs baseline: 1.5551x; 1.5551x over previous
#include <cuda_runtime.h>

#define A_DIM 1024
#define T_DIM 256
#define CS 384
#define CZ 128
#define CA 128
#define CP 16
#define EPS 1e-5f

// ---- device scratch ----
__device__ int   g_tok[A_DIM];
__device__ float g_ys[T_DIM * CA];
__device__ float g_w[T_DIM * T_DIM * CP];
__device__ unsigned g_ctr_pre;   // ys+tok producers done (target 64)
__device__ unsigned g_ctr_all;   // all producers done (target 1088)
__device__ unsigned g_done;      // consumers done (target 2176) -> reset

#define FMA2(d, a, b) asm("fma.rn.f32x2 %0, %1, %2, %0;" : "+l"(d) : "l"(a), "l"(b))
#define ADD2(d, a)    asm("add.rn.f32x2 %0, %0, %1;" : "+l"(d) : "l"(a))

__device__ __forceinline__ float hsum2(unsigned long long v) {
    float lo, hi;
    asm("mov.b64 {%0, %1}, %2;" : "=f"(lo), "=f"(hi) : "l"(v));
    return lo + hi;
}

__device__ __forceinline__ unsigned ld_acq(const unsigned* p) {
    unsigned v;
    asm volatile("ld.acquire.gpu.global.u32 %0, [%1];" : "=r"(v) : "l"(p));
    return v;
}

#define YS_BLOCKS 32
#define TOK_BLOCKS 32
#define KW_BLOCKS 1024        // 64 rows each, 1 row/thread
#define PROD_BLOCKS (YS_BLOCKS + TOK_BLOCKS + KW_BLOCKS)   // 1088
#define CLQL_BLOCKS 128
#define PLM_BLOCKS 2048
#define CONS_BLOCKS (CLQL_BLOCKS + PLM_BLOCKS)             // 2176
#define GWPAD 132

__global__ __launch_bounds__(256) void k_all(
    const float* __restrict__ zij, const float* __restrict__ gz,
    const float* __restrict__ bz, const float* __restrict__ Wz,
    const float* __restrict__ s_trunk, const float* __restrict__ gs,
    const float* __restrict__ bs, const float* __restrict__ Ws,
    const float* __restrict__ a2t,
    const float* __restrict__ cl, const float* __restrict__ ql,
    const float* __restrict__ rl, const float* __restrict__ Wr,
    const float* __restrict__ plm,
    float* __restrict__ out_cl, float* __restrict__ out_ql,
    float* __restrict__ out_plm) {
    int tid = threadIdx.x;
    int bx = blockIdx.x;

    // ================== producers ==================
    if (bx < YS_BLOCKS) {
        // ---------- ys: 8 tokens per block ----------
        __shared__ float sn[8][CS];
        __shared__ float mv[8][2];
        int t0 = bx * 8;
        int w = tid >> 5, lane = tid & 31;
        {
            int t = t0 + w;
            float s1 = 0.f, s2 = 0.f;
#pragma unroll
            for (int i = 0; i < 12; i++) {
                int k = lane + 32 * i;
                float x = s_trunk[(size_t)t * CS + k];
                sn[w][k] = x;
                s1 += x;
                s2 = fmaf(x, x, s2);
            }
            for (int d = 16; d; d >>= 1) {
                s1 += __shfl_down_sync(0xffffffffu, s1, d);
                s2 += __shfl_down_sync(0xffffffffu, s2, d);
            }
            if (lane == 0) {
                float m = s1 * (1.0f / CS);
                float v = s2 * (1.0f / CS) - m * m;
                mv[w][0] = m;
                mv[w][1] = rsqrtf(v + EPS);
            }
        }
        __syncthreads();
#pragma unroll
        for (int i = 0; i < 12; i++) {
            int idx = tid + 256 * i;
            int r = idx / CS, k = idx - r * CS;
            sn[r][k] = (sn[r][k] - mv[r][0]) * mv[r][1] * gs[k] + bs[k];
        }
        __syncthreads();
        int j = tid & 127;
        int h = tid >> 7;
        float a0 = 0.f, a1 = 0.f, a2 = 0.f, a3 = 0.f;
#pragma unroll 16
        for (int k = 0; k < CS; k++) {
            float wv = Ws[(size_t)k * CA + j];
            a0 = fmaf(sn[4*h  ][k], wv, a0);
            a1 = fmaf(sn[4*h+1][k], wv, a1);
            a2 = fmaf(sn[4*h+2][k], wv, a2);
            a3 = fmaf(sn[4*h+3][k], wv, a3);
        }
        g_ys[(size_t)(t0 + 4*h    ) * CA + j] = a0;
        g_ys[(size_t)(t0 + 4*h + 1) * CA + j] = a1;
        g_ys[(size_t)(t0 + 4*h + 2) * CA + j] = a2;
        g_ys[(size_t)(t0 + 4*h + 3) * CA + j] = a3;
        __syncthreads();
        __threadfence();
        if (tid == 0) {
            atomicAdd(&g_ctr_pre, 1u);
            atomicAdd(&g_ctr_all, 1u);
        }
        return;
    }

    if (bx < YS_BLOCKS + TOK_BLOCKS) {
        int row0 = (bx - YS_BLOCKS) * 32;
#pragma unroll
        for (int i = 0; i < 32; i++) {
            float v = a2t[(size_t)(row0 + i) * T_DIM + tid];
            if (v > 0.5f) g_tok[row0 + i] = tid;
        }
        __syncthreads();
        __threadfence();
        if (tid == 0) {
            atomicAdd(&g_ctr_pre, 1u);
            atomicAdd(&g_ctr_all, 1u);
        }
        return;
    }

    if (bx < PROD_BLOCKS) {
        // ---------- k_w: 64 rows per block, 1 row per thread ----------
        __shared__ __align__(16) float GWs[CP * GWPAD];
        __shared__ float BWs[CP], CgWs[CP];
        __shared__ float pbw[256], pcg[256];
        {
            int j = tid & 15;
            float pb = 0.f, pc = 0.f;
#pragma unroll
            for (int i = 0; i < 8; i++) {
                int idx = tid + 256 * i;
                int k = idx >> 4;
                float wv = Wz[idx];
                float gw = gz[k] * wv;
                GWs[j * GWPAD + k] = gw;
                pb = fmaf(bz[k], wv, pb);
                pc += gw;
            }
            pbw[tid] = pb;
            pcg[tid] = pc;
        }
        __syncthreads();
        if (tid < CP) {
            float sb = 0.f, sc = 0.f;
#pragma unroll
            for (int i = 0; i < 16; i++) {
                sb += pbw[tid + 16 * i];
                sc += pcg[tid + 16 * i];
            }
            BWs[tid] = sb;
            CgWs[tid] = sc;
        }
        __syncthreads();

        int q = tid & 3, rp = tid >> 2;
        size_t row = (size_t)(bx - YS_BLOCKS - TOK_BLOCKS) * 64 + rp;
        const ulonglong2* z = (const ulonglong2*)(zij + row * CZ);
        const ulonglong2* G = (const ulonglong2*)GWs;

        unsigned long long acc[CP];
#pragma unroll
        for (int j = 0; j < CP; j++) acc[j] = 0ull;
        unsigned long long sS = 0ull, sQ = 0ull;

#pragma unroll
        for (int c = 0; c < 8; c++) {
            ulonglong2 zv = z[q + 4 * c];
            ADD2(sS, zv.x); ADD2(sS, zv.y);
            FMA2(sQ, zv.x, zv.x); FMA2(sQ, zv.y, zv.y);
#pragma unroll
            for (int j = 0; j < CP; j++) {
                ulonglong2 g = G[j * 33 + q + 4 * c];
                FMA2(acc[j], zv.x, g.x); FMA2(acc[j], zv.y, g.y);
            }
        }

        float s1 = hsum2(sS), s2 = hsum2(sQ);
        s1 += __shfl_xor_sync(0xffffffffu, s1, 1);
        s2 += __shfl_xor_sync(0xffffffffu, s2, 1);
        s1 += __shfl_xor_sync(0xffffffffu, s1, 2);
        s2 += __shfl_xor_sync(0xffffffffu, s2, 2);
        float m  = s1 * (1.0f / CZ);
        float vv = s2 * (1.0f / CZ) - m * m;
        float ri = rsqrtf(vv + EPS);

        float f[16];
#pragma unroll
        for (int j = 0; j < CP; j++) f[j] = hsum2(acc[j]);

        bool hi = (q & 1);
        float kk[8];
#pragma unroll
        for (int i = 0; i < 8; i++) {
            float lo = f[i], hih = f[8 + i];
            float mine = hi ? hih : lo;
            float send = hi ? lo : hih;
            kk[i] = mine + __shfl_xor_sync(0xffffffffu, send, 1);
        }
        bool hi2 = (q & 2);
        float g4[4];
#pragma unroll
        for (int i = 0; i < 4; i++) {
            float lo = kk[i], hih = kk[4 + i];
            float mine = hi2 ? hih : lo;
            float send = hi2 ? lo : hih;
            g4[i] = mine + __shfl_xor_sync(0xffffffffu, send, 2);
        }
        int jb = (hi ? 8 : 0) + (hi2 ? 4 : 0);

        float4 o;
        o.x = ri * (g4[0] - m * CgWs[jb    ]) + BWs[jb    ];
        o.y = ri * (g4[1] - m * CgWs[jb + 1]) + BWs[jb + 1];
        o.z = ri * (g4[2] - m * CgWs[jb + 2]) + BWs[jb + 2];
        o.w = ri * (g4[3] - m * CgWs[jb + 3]) + BWs[jb + 3];
        *((float4*)(g_w + row * CP + jb)) = o;
        __syncthreads();
        __threadfence();
        if (tid == 0) atomicAdd(&g_ctr_all, 1u);
        return;
    }

    // ================== consumers ==================
    if (bx < PROD_BLOCKS + CLQL_BLOCKS) {
        int a = (bx - PROD_BLOCKS) * 8 + (tid >> 5);
        int j4 = tid & 31;
        size_t idx = (size_t)a * 32 + j4;
        const float4* cl4 = (const float4*)cl;
        const float4* ql4 = (const float4*)ql;
        const float4* ys4 = (const float4*)g_ys;
        const float4* Wr4 = (const float4*)Wr;
        float4 c = cl4[idx];
        float4 qv = ql4[idx];
        float r0 = rl[a * 3], r1 = rl[a * 3 + 1], r2 = rl[a * 3 + 2];
        float4 w0 = Wr4[j4], w1 = Wr4[32 + j4], w2 = Wr4[64 + j4];
        float4 oq;
        oq.x = qv.x + r0 * w0.x + r1 * w1.x + r2 * w2.x;
        oq.y = qv.y + r0 * w0.y + r1 * w1.y + r2 * w2.y;
        oq.z = qv.z + r0 * w0.z + r1 * w1.z + r2 * w2.z;
        oq.w = qv.w + r0 * w0.w + r1 * w1.w + r2 * w2.w;
        ((float4*)out_ql)[idx] = oq;
        if (tid == 0) {
            while (ld_acq(&g_ctr_pre) < (unsigned)(YS_BLOCKS + TOK_BLOCKS))
                __nanosleep(64);
        }
        __syncthreads();
        int ta = g_tok[a];
        float4 y = ys4[(size_t)ta * 32 + j4];
        float4 oc;
        oc.x = c.x + y.x; oc.y = c.y + y.y; oc.z = c.z + y.z; oc.w = c.w + y.w;
        ((float4*)out_cl)[idx] = oc;
        if (tid == 0) {
            unsigned d = atomicAdd(&g_done, 1u);
            if (d == CONS_BLOCKS - 1) { g_ctr_pre = 0; g_ctr_all = 0; g_done = 0; }
        }
        return;
    }

    // ---------- plm consumer: 8 a-rows x 64 b ----------
    {
        int pm = bx - PROD_BLOCKS - CLQL_BLOCKS;
        int a0 = (pm >> 4) * 8;
        int b = (pm & 15) * 64 + (tid >> 2);
        int c4 = tid & 3;
        const float4* p4 = (const float4*)plm;
        const float4* w4 = (const float4*)g_w;
        float4* o4 = (float4*)out_plm;

        // prefetch plm tiles (streaming) — overlaps with producer compute
        float4 p[8];
#pragma unroll
        for (int i = 0; i < 8; i++)
            p[i] = __ldcs(&p4[((size_t)(a0 + i) * A_DIM + b) * 4 + c4]);

        if (tid == 0) {
            while (ld_acq(&g_ctr_all) < (unsigned)PROD_BLOCKS)
                __nanosleep(64);
        }
        __syncthreads();

        int tb = g_tok[b];
        int ta[8];
#pragma unroll
        for (int i = 0; i < 8; i++) ta[i] = g_tok[a0 + i];

        float4 w[8];
#pragma unroll
        for (int i = 0; i < 8; i++)
            w[i] = w4[((size_t)ta[i] * T_DIM + tb) * 4 + c4];
#pragma unroll
        for (int i = 0; i < 8; i++) {
            float4 o;
            o.x = p[i].x + w[i].x; o.y = p[i].y + w[i].y;
            o.z = p[i].z + w[i].z; o.w = p[i].w + w[i].w;
            __stcs(&o4[((size_t)(a0 + i) * A_DIM + b) * 4 + c4], o);
        }
        if (tid == 0) {
            unsigned d = atomicAdd(&g_done, 1u);
            if (d == CONS_BLOCKS - 1) { g_ctr_pre = 0; g_ctr_all = 0; g_done = 0; }
        }
    }
}

extern "C" void kernel_launch(void* const* d_in, const int* in_sizes, int n_in,
                              void* d_out, int out_size) {
    const float* a2t     = (const float*)d_in[0];
    const float* cl      = (const float*)d_in[1];
    const float* plm     = (const float*)d_in[2];
    const float* ql      = (const float*)d_in[3];
    const float* s_trunk = (const float*)d_in[4];
    const float* zij     = (const float*)d_in[5];
    const float* rl      = (const float*)d_in[6];
    const float* ln_s_g  = (const float*)d_in[7];
    const float* ln_s_b  = (const float*)d_in[8];
    const float* Ws      = (const float*)d_in[9];
    const float* ln_z_g  = (const float*)d_in[10];
    const float* ln_z_b  = (const float*)d_in[11];
    const float* Wz      = (const float*)d_in[12];
    const float* Wr      = (const float*)d_in[13];
    float* out     = (float*)d_out;
    float* out_cl  = out;
    float* out_plm = out + A_DIM * CA;
    float* out_ql  = out_plm + (size_t)A_DIM * A_DIM * CP;

    k_all<<<PROD_BLOCKS + CONS_BLOCKS, 256>>>(
        zij, ln_z_g, ln_z_b, Wz, s_trunk, ln_s_g, ln_s_b, Ws, a2t,
        cl, ql, rl, Wr, plm, out_cl, out_ql, out_plm);
}